// round 1
// baseline (speedup 1.0000x reference)
#include <cuda_runtime.h>

#define HN 16
#define DD 64
#define BQ 64
#define BK 64
#define LDS_ 68   // smem row stride in floats (pad for bank conflicts, float4-aligned)

__global__ __launch_bounds__(256) void varlen_attn_kernel(
    const float* __restrict__ qg, const float* __restrict__ kg, const float* __restrict__ vg,
    const int* __restrict__ cuq, const int* __restrict__ cuk,
    float* __restrict__ out, int T, int ncu)
{
    extern __shared__ float sm[];
    float* qT = sm;                    // [DD][LDS_]  d-major: qT[d*LDS_ + qrow]
    float* kT = qT + DD * LDS_;        // [DD][LDS_]  d-major: kT[d*LDS_ + krow]
    float* vs = kT + DD * LDS_;        // [BK][LDS_]  k-major: vs[k*LDS_ + d]
    float* ps = vs + BK * LDS_;        // [BQ][LDS_]  probs:  ps[q*LDS_ + k]
    int* qseg = (int*)(ps + BQ * LDS_);
    int* kseg = qseg + BQ;
    int* cus  = kseg + BK;             // up to 64 entries

    const int tid = threadIdx.x;
    const int tx = tid & 15;           // 16 col groups (k / d)
    const int ty = tid >> 4;           // 16 row groups (q)
    const int h  = blockIdx.y;
    const int q0 = blockIdx.x * BQ;

    if (tid < ncu) cus[tid] = cuk[tid];

    // segment id per query row (matches searchsorted(cu[1:], t, 'right'))
    if (tid < BQ) {
        int t = q0 + tid;
        int s = -2;
        if (t < T) {
            s = 0;
            for (int i = 1; i < ncu - 1; i++) s += (cuq[i] <= t);
        }
        qseg[tid] = s;
    }

    // load Q tile (d-major), pre-scaled by 1/sqrt(D)
    for (int idx = tid; idx < BQ * DD; idx += 256) {
        int r = idx >> 6, d = idx & 63;
        int t = q0 + r;
        float val = (t < T) ? qg[(size_t)t * (HN * DD) + h * DD + d] * 0.125f : 0.f;
        qT[d * LDS_ + r] = val;
    }
    __syncthreads();

    const int lastq = min(BQ - 1, T - 1 - q0);
    const int s0 = qseg[0];
    const int s1 = qseg[lastq];
    const int kbeg = cus[s0];
    const int kend = cus[s1 + 1];

    float m_i[4], l_i[4], o[4][4];
    #pragma unroll
    for (int i = 0; i < 4; i++) {
        m_i[i] = -INFINITY;
        l_i[i] = 0.f;
        #pragma unroll
        for (int j = 0; j < 4; j++) o[i][j] = 0.f;
    }

    for (int kt = (kbeg / BK) * BK; kt < kend; kt += BK) {
        __syncthreads();   // protect kT/vs/ps from previous iteration's readers

        // load K (d-major) and V (k-major)
        for (int idx = tid; idx < BK * DD; idx += 256) {
            int r = idx >> 6, d = idx & 63;
            int t = kt + r;
            float kv = 0.f, vv = 0.f;
            if (t < T) {
                size_t base = (size_t)t * (HN * DD) + h * DD + d;
                kv = kg[base];
                vv = vg[base];
            }
            kT[d * LDS_ + r] = kv;
            vs[r * LDS_ + d] = vv;
        }
        if (tid < BK) {
            int t = kt + tid;
            int s = -1;
            if (t < T) {
                s = 0;
                for (int i = 1; i < ncu - 1; i++) s += (cus[i] <= t);
            }
            kseg[tid] = s;
        }
        __syncthreads();

        // ---- S = Q K^T  (4x4 register microtile per thread) ----
        float acc[4][4];
        #pragma unroll
        for (int i = 0; i < 4; i++)
            #pragma unroll
            for (int j = 0; j < 4; j++) acc[i][j] = 0.f;

        #pragma unroll 8
        for (int d = 0; d < DD; d++) {
            float4 a = *(const float4*)&qT[d * LDS_ + ty * 4];
            float4 b = *(const float4*)&kT[d * LDS_ + tx * 4];
            float av[4] = {a.x, a.y, a.z, a.w};
            float bv[4] = {b.x, b.y, b.z, b.w};
            #pragma unroll
            for (int i = 0; i < 4; i++)
                #pragma unroll
                for (int j = 0; j < 4; j++)
                    acc[i][j] = fmaf(av[i], bv[j], acc[i][j]);
        }

        // ---- segment mask ----
        int qs[4], ks[4];
        #pragma unroll
        for (int i = 0; i < 4; i++) qs[i] = qseg[ty * 4 + i];
        #pragma unroll
        for (int j = 0; j < 4; j++) ks[j] = kseg[tx * 4 + j];
        #pragma unroll
        for (int i = 0; i < 4; i++)
            #pragma unroll
            for (int j = 0; j < 4; j++)
                if (qs[i] != ks[j]) acc[i][j] = -1e30f;

        // ---- online softmax (row reductions over 16 lanes) ----
        #pragma unroll
        for (int i = 0; i < 4; i++) {
            float tmax = fmaxf(fmaxf(acc[i][0], acc[i][1]), fmaxf(acc[i][2], acc[i][3]));
            #pragma unroll
            for (int msk = 8; msk >= 1; msk >>= 1)
                tmax = fmaxf(tmax, __shfl_xor_sync(0xffffffffu, tmax, msk));

            float mnew = fmaxf(m_i[i], tmax);
            float sc = __expf(m_i[i] - mnew);
            m_i[i] = mnew;

            float rs = 0.f;
            #pragma unroll
            for (int j = 0; j < 4; j++) {
                acc[i][j] = __expf(acc[i][j] - mnew);
                rs += acc[i][j];
            }
            #pragma unroll
            for (int msk = 8; msk >= 1; msk >>= 1)
                rs += __shfl_xor_sync(0xffffffffu, rs, msk);

            l_i[i] = l_i[i] * sc + rs;
            #pragma unroll
            for (int j = 0; j < 4; j++) o[i][j] *= sc;

            *(float4*)&ps[(ty * 4 + i) * LDS_ + tx * 4] =
                make_float4(acc[i][0], acc[i][1], acc[i][2], acc[i][3]);
        }
        __syncthreads();

        // ---- O += P V ----
        #pragma unroll 8
        for (int kk = 0; kk < BK; kk++) {
            float4 vv = *(const float4*)&vs[kk * LDS_ + tx * 4];
            #pragma unroll
            for (int i = 0; i < 4; i++) {
                float p = ps[(ty * 4 + i) * LDS_ + kk];
                o[i][0] = fmaf(p, vv.x, o[i][0]);
                o[i][1] = fmaf(p, vv.y, o[i][1]);
                o[i][2] = fmaf(p, vv.z, o[i][2]);
                o[i][3] = fmaf(p, vv.w, o[i][3]);
            }
        }
    }

    // ---- epilogue: normalize and store ----
    #pragma unroll
    for (int i = 0; i < 4; i++) {
        int t = q0 + ty * 4 + i;
        if (t < T) {
            float inv = 1.f / l_i[i];
            float4 r = make_float4(o[i][0] * inv, o[i][1] * inv, o[i][2] * inv, o[i][3] * inv);
            *(float4*)&out[(size_t)t * (HN * DD) + h * DD + tx * 4] = r;
        }
    }
}

extern "C" void kernel_launch(void* const* d_in, const int* in_sizes, int n_in,
                              void* d_out, int out_size)
{
    const float* q = (const float*)d_in[0];
    const float* k = (const float*)d_in[1];
    const float* v = (const float*)d_in[2];
    const int* cuq = (const int*)d_in[3];
    const int* cuk = (const int*)d_in[4];

    int T = in_sizes[0] / (HN * DD);
    int ncu = in_sizes[3];

    size_t smem = (size_t)(2 * DD * LDS_ + BK * LDS_ + BQ * LDS_) * sizeof(float)
                + (size_t)(BQ + BK + 64) * sizeof(int);

    cudaFuncSetAttribute(varlen_attn_kernel,
                         cudaFuncAttributeMaxDynamicSharedMemorySize, (int)smem);

    dim3 grid((T + BQ - 1) / BQ, HN);
    varlen_attn_kernel<<<grid, 256, smem>>>(q, k, v, cuq, cuk, (float*)d_out, T, ncu);
}

// round 3
// speedup vs baseline: 3.0045x; 3.0045x over previous
#include <cuda_runtime.h>
#include <cstdint>

#define HN 16
#define DD 64
#define BQ 128
#define BK 64
#define NT 256
#define QSCALE 0.1803368801111f   // (1/8) * log2(e)

// smem layout (floats)
#define OFF_K 0                    // [64][68]
#define OFF_V 4352                 // [64][72]
#define OFF_P 8960                 // 8 warps x [16][68]
#define OFF_KSEG 17664             // 64 ints
#define OFF_CUS  (17664 + 64)      // 64 ints
#define SMEM_BYTES ((17664 + 128) * 4)

__device__ __forceinline__ uint32_t f2tf(float x) {
    uint32_t r; asm("cvt.rna.tf32.f32 %0, %1;" : "=r"(r) : "f"(x)); return r;
}
__device__ __forceinline__ float ex2f(float x) {
    float y; asm("ex2.approx.ftz.f32 %0, %1;" : "=f"(y) : "f"(x)); return y;
}
__device__ __forceinline__ void mma8(float* c, const uint32_t* a, uint32_t b0, uint32_t b1) {
    asm volatile("mma.sync.aligned.m16n8k8.row.col.f32.tf32.tf32.f32 "
                 "{%0,%1,%2,%3}, {%4,%5,%6,%7}, {%8,%9}, {%0,%1,%2,%3};"
                 : "+f"(c[0]), "+f"(c[1]), "+f"(c[2]), "+f"(c[3])
                 : "r"(a[0]), "r"(a[1]), "r"(a[2]), "r"(a[3]), "r"(b0), "r"(b1));
}

__global__ __launch_bounds__(NT, 2) void varlen_attn_mma(
    const float* __restrict__ qg, const float* __restrict__ kg, const float* __restrict__ vg,
    const int* __restrict__ cuq, const int* __restrict__ cuk,
    float* __restrict__ out, int T, int ncu)
{
    extern __shared__ float smf[];
    float* Ks = smf + OFF_K;
    float* Vs = smf + OFF_V;
    int* kseg = (int*)(smf + OFF_KSEG);
    int* cus  = (int*)(smf + OFF_CUS);

    const int tid  = threadIdx.x;
    const int w    = tid >> 5;
    const int lane = tid & 31;
    const int g    = lane >> 2;     // groupID (row within fragment)
    const int tig  = lane & 3;      // thread in group
    float* Pw = smf + OFF_P + w * (16 * 68);

    const int h  = blockIdx.y;
    const int q0 = blockIdx.x * BQ;

    if (tid < ncu) cus[tid] = cuk[tid];
    __syncthreads();

    // my two q-rows and their segments; block k-span
    const int t0g = q0 + w * 16 + g;
    const int t1g = t0g + 8;
    int qs0 = 0, qs1 = 0, sfirst = 0, slast = 0;
    {
        const int tl = min(q0 + BQ - 1, T - 1);
        for (int i = 1; i < ncu - 1; i++) {
            int c = cus[i];
            qs0 += (c <= t0g); qs1 += (c <= t1g);
            sfirst += (c <= q0); slast += (c <= tl);
        }
    }
    const int kbeg = cus[sfirst];
    const int kend = cus[slast + 1];

    // ---- Q fragments (held in registers for the whole block) ----
    uint32_t qf[8][4];
    {
        const float* qp0 = qg + (size_t)t0g * (HN * DD) + h * DD;
        const float* qp1 = qg + (size_t)t1g * (HN * DD) + h * DD;
        #pragma unroll
        for (int ks = 0; ks < 8; ks++) {
            int d = ks * 8 + tig;
            qf[ks][0] = f2tf(qp0[d] * QSCALE);
            qf[ks][1] = f2tf(qp1[d] * QSCALE);
            qf[ks][2] = f2tf(qp0[d + 4] * QSCALE);
            qf[ks][3] = f2tf(qp1[d + 4] * QSCALE);
        }
    }

    float oacc[8][4];
    #pragma unroll
    for (int n = 0; n < 8; n++)
        #pragma unroll
        for (int j = 0; j < 4; j++) oacc[n][j] = 0.f;
    float l0 = 0.f, l1 = 0.f;

    for (int kt = (kbeg / BK) * BK; kt < kend; kt += BK) {
        __syncthreads();   // previous iteration's smem reads complete

        // ---- load K,V tile (pre-converted to tf32), kseg ----
        #pragma unroll
        for (int i = 0; i < 4; i++) {
            int idx = tid + i * NT;         // 0..1023
            int r = idx >> 4, c4 = idx & 15;
            size_t base = (size_t)(kt + r) * (HN * DD) + h * DD + c4 * 4;
            float4 kv = *(const float4*)(kg + base);
            float4 vv = *(const float4*)(vg + base);
            float* kd = Ks + r * 68 + c4 * 4;
            kd[0] = __uint_as_float(f2tf(kv.x));
            kd[1] = __uint_as_float(f2tf(kv.y));
            kd[2] = __uint_as_float(f2tf(kv.z));
            kd[3] = __uint_as_float(f2tf(kv.w));
            float* vd = Vs + r * 72 + c4 * 4;
            vd[0] = __uint_as_float(f2tf(vv.x));
            vd[1] = __uint_as_float(f2tf(vv.y));
            vd[2] = __uint_as_float(f2tf(vv.z));
            vd[3] = __uint_as_float(f2tf(vv.w));
        }
        if (tid < BK) {
            int t = kt + tid;
            int s = 0;
            for (int i = 1; i < ncu - 1; i++) s += (cus[i] <= t);
            kseg[tid] = s;
        }
        __syncthreads();

        // ---- S = Q K^T  (tf32 mma, 8 n-tiles x 8 k-steps) ----
        float sacc[8][4];
        #pragma unroll
        for (int n = 0; n < 8; n++)
            #pragma unroll
            for (int j = 0; j < 4; j++) sacc[n][j] = 0.f;

        #pragma unroll
        for (int ks = 0; ks < 8; ks++) {
            #pragma unroll
            for (int n = 0; n < 8; n++) {
                const float* bp = Ks + (n * 8 + g) * 68 + ks * 8 + tig;
                mma8(sacc[n], qf[ks], __float_as_uint(bp[0]), __float_as_uint(bp[4]));
            }
        }

        // ---- mask + exp2 + write P (warp-private region) ----
        #pragma unroll
        for (int n = 0; n < 8; n++) {
            int kc = n * 8 + 2 * tig;
            int ks0 = kseg[kc], ks1 = kseg[kc + 1];
            float p00 = (ks0 == qs0) ? ex2f(sacc[n][0]) : 0.f;
            float p01 = (ks1 == qs0) ? ex2f(sacc[n][1]) : 0.f;
            float p10 = (ks0 == qs1) ? ex2f(sacc[n][2]) : 0.f;
            float p11 = (ks1 == qs1) ? ex2f(sacc[n][3]) : 0.f;
            p00 = __uint_as_float(f2tf(p00));
            p01 = __uint_as_float(f2tf(p01));
            p10 = __uint_as_float(f2tf(p10));
            p11 = __uint_as_float(f2tf(p11));
            l0 += p00 + p01;
            l1 += p10 + p11;
            *(float2*)(Pw + g * 68 + kc)       = make_float2(p00, p01);
            *(float2*)(Pw + (g + 8) * 68 + kc) = make_float2(p10, p11);
        }
        __syncwarp();

        // ---- O += P V ----
        #pragma unroll
        for (int ks = 0; ks < 8; ks++) {
            uint32_t a[4];
            const float* ap0 = Pw + g * 68 + ks * 8 + tig;
            const float* ap1 = ap0 + 8 * 68;
            a[0] = __float_as_uint(ap0[0]);
            a[1] = __float_as_uint(ap1[0]);
            a[2] = __float_as_uint(ap0[4]);
            a[3] = __float_as_uint(ap1[4]);
            #pragma unroll
            for (int n = 0; n < 8; n++) {
                const float* bp = Vs + (ks * 8 + tig) * 72 + n * 8 + g;
                mma8(oacc[n], a, __float_as_uint(bp[0]), __float_as_uint(bp[4 * 72]));
            }
        }
    }

    // ---- epilogue: row sums across the 4-lane group, normalize, store ----
    l0 += __shfl_xor_sync(0xffffffffu, l0, 1);
    l0 += __shfl_xor_sync(0xffffffffu, l0, 2);
    l1 += __shfl_xor_sync(0xffffffffu, l1, 1);
    l1 += __shfl_xor_sync(0xffffffffu, l1, 2);
    float i0 = 1.f / l0;
    float i1 = 1.f / l1;

    float* o0 = out + (size_t)t0g * (HN * DD) + h * DD;
    float* o1 = out + (size_t)t1g * (HN * DD) + h * DD;
    #pragma unroll
    for (int n = 0; n < 8; n++) {
        int c = n * 8 + 2 * tig;
        *(float2*)(o0 + c) = make_float2(oacc[n][0] * i0, oacc[n][1] * i0);
        *(float2*)(o1 + c) = make_float2(oacc[n][2] * i1, oacc[n][3] * i1);
    }
}

extern "C" void kernel_launch(void* const* d_in, const int* in_sizes, int n_in,
                              void* d_out, int out_size)
{
    const float* q = (const float*)d_in[0];
    const float* k = (const float*)d_in[1];
    const float* v = (const float*)d_in[2];
    const int* cuq = (const int*)d_in[3];
    const int* cuk = (const int*)d_in[4];

    int T = in_sizes[0] / (HN * DD);
    int ncu = in_sizes[3];

    cudaFuncSetAttribute(varlen_attn_mma,
                         cudaFuncAttributeMaxDynamicSharedMemorySize, SMEM_BYTES);

    dim3 grid((T + BQ - 1) / BQ, HN);
    varlen_attn_mma<<<grid, NT, SMEM_BYTES>>>(q, k, v, cuq, cuk, (float*)d_out, T, ncu);
}